// round 2
// baseline (speedup 1.0000x reference)
#include <cuda_runtime.h>
#include <cuda_fp16.h>
#include <mma.h>

using namespace nvcuda;

// Problem dims (fixed by the reference)
#define BATCH 8
#define SEQ   2048
#define KDIM  4096
#define MDIM  4096
#define NDIM  (BATCH * SEQ)   // 16384

// GEMM tiling
#define BM 128
#define BN 128
#define BK 32
#define PAD 8                 // smem row padding (halfs)
#define THREADS 256

// fp16 scratch (device globals: allocation-free, allowed per harness rules)
__device__ __align__(16) __half g_Wh[(size_t)MDIM * KDIM];        // 32 MB
__device__ __align__(16) __half g_Xh[(size_t)NDIM * KDIM];        // 128 MB

// ---------------------------------------------------------------------------
// Kernel 1: W*mask -> fp16 (vectorized, grid-stride)
// Mask arrives as int32 (harness upcasts bool): one int per weight element.
// ---------------------------------------------------------------------------
__global__ void convert_w_kernel(const float* __restrict__ w,
                                 const int* __restrict__ mask) {
    size_t total4 = (size_t)MDIM * KDIM / 4;
    for (size_t i = (size_t)blockIdx.x * blockDim.x + threadIdx.x;
         i < total4;
         i += (size_t)gridDim.x * blockDim.x) {
        float4 wv = reinterpret_cast<const float4*>(w)[i];
        int4   mv = reinterpret_cast<const int4*>(mask)[i];
        float a = mv.x ? wv.x : 0.0f;
        float b = mv.y ? wv.y : 0.0f;
        float c = mv.z ? wv.z : 0.0f;
        float d = mv.w ? wv.w : 0.0f;
        __half2* o = reinterpret_cast<__half2*>(&g_Wh[i * 4]);
        o[0] = __floats2half2_rn(a, b);
        o[1] = __floats2half2_rn(c, d);
    }
}

// ---------------------------------------------------------------------------
// Kernel 2: x -> fp16 (vectorized, grid-stride)
// ---------------------------------------------------------------------------
__global__ void convert_x_kernel(const float* __restrict__ x) {
    size_t total4 = (size_t)NDIM * KDIM / 4;
    for (size_t i = (size_t)blockIdx.x * blockDim.x + threadIdx.x;
         i < total4;
         i += (size_t)gridDim.x * blockDim.x) {
        float4 xv = reinterpret_cast<const float4*>(x)[i];
        __half2* o = reinterpret_cast<__half2*>(&g_Xh[i * 4]);
        o[0] = __floats2half2_rn(xv.x, xv.y);
        o[1] = __floats2half2_rn(xv.z, xv.w);
    }
}

// ---------------------------------------------------------------------------
// Kernel 3: GEMM  C[m, n] = sum_k Wh[m,k] * Xh[n,k]
// A = Wh [M, K] row-major (k contiguous)   -> wmma matrix_a row_major
// B = Xh [N, K] row-major (k contiguous)   == col-major K x N -> matrix_b col_major
// Output layout [B, M, S]: n = b*SEQ + s; BN=128 divides SEQ so each block
// stays within one batch index.
// ---------------------------------------------------------------------------
__global__ void __launch_bounds__(THREADS, 2)
gemm_wmma_kernel(float* __restrict__ out) {
    __shared__ __half As[BM][BK + PAD];
    __shared__ __half Bs[BN][BK + PAD];

    const int nBase = blockIdx.x * BN;
    const int mBase = blockIdx.y * BM;

    const int tid = threadIdx.x;
    const int wid = tid >> 5;
    // 8 warps: 2 (m) x 4 (n); warp tile = 64 x 32
    const int wm = wid >> 2;        // 0..1
    const int wn = wid & 3;         // 0..3

    wmma::fragment<wmma::accumulator, 16, 16, 16, float> acc[4][2];
#pragma unroll
    for (int i = 0; i < 4; i++)
#pragma unroll
        for (int j = 0; j < 2; j++)
            wmma::fill_fragment(acc[i][j], 0.0f);

    const uint4* Ag = reinterpret_cast<const uint4*>(&g_Wh[(size_t)mBase * KDIM]);
    const uint4* Bg = reinterpret_cast<const uint4*>(&g_Xh[(size_t)nBase * KDIM]);
    const int gld = KDIM / 8;       // uint4 per global row

    for (int k0 = 0; k0 < KDIM; k0 += BK) {
        // Load A+B tiles: 128 rows x 32 halfs = 512 uint4 each; 2 per thread
        {
            const int kq = k0 / 8;  // uint4 offset within row
#pragma unroll
            for (int r = 0; r < 2; r++) {
                int idx = tid + r * THREADS;     // 0..511
                int row = idx >> 2;
                int c   = idx & 3;
                uint4 v = Ag[(size_t)row * gld + kq + c];
                *reinterpret_cast<uint4*>(&As[row][c * 8]) = v;
                uint4 w = Bg[(size_t)row * gld + kq + c];
                *reinterpret_cast<uint4*>(&Bs[row][c * 8]) = w;
            }
        }
        __syncthreads();

#pragma unroll
        for (int kk = 0; kk < BK; kk += 16) {
            wmma::fragment<wmma::matrix_a, 16, 16, 16, __half, wmma::row_major> af[4];
            wmma::fragment<wmma::matrix_b, 16, 16, 16, __half, wmma::col_major> bf[2];
#pragma unroll
            for (int i = 0; i < 4; i++)
                wmma::load_matrix_sync(af[i], &As[wm * 64 + i * 16][kk], BK + PAD);
#pragma unroll
            for (int j = 0; j < 2; j++)
                wmma::load_matrix_sync(bf[j], &Bs[wn * 32 + j * 16][kk], BK + PAD);
#pragma unroll
            for (int i = 0; i < 4; i++)
#pragma unroll
                for (int j = 0; j < 2; j++)
                    wmma::mma_sync(acc[i][j], af[i], bf[j], acc[i][j]);
        }
        __syncthreads();
    }

    // Store: out[b, m, s] with b = nBase/SEQ, s = n - b*SEQ
    const int b = nBase / SEQ;
    const int sBase = nBase - b * SEQ + wn * 32;
    float* outp = out + ((size_t)b * MDIM + mBase + wm * 64) * SEQ + sBase;
#pragma unroll
    for (int i = 0; i < 4; i++)
#pragma unroll
        for (int j = 0; j < 2; j++)
            wmma::store_matrix_sync(outp + (size_t)i * 16 * SEQ + j * 16,
                                    acc[i][j], SEQ, wmma::mem_row_major);
}

// ---------------------------------------------------------------------------
// Launch
// ---------------------------------------------------------------------------
extern "C" void kernel_launch(void* const* d_in, const int* in_sizes, int n_in,
                              void* d_out, int out_size) {
    const float* x    = (const float*)d_in[0];   // [B, S, K]
    const float* w    = (const float*)d_in[1];   // [M, K]
    const int*   mask = (const int*)d_in[2];     // [M, K] bool upcast to int32
    float* out = (float*)d_out;                  // [B, M, S]

    convert_w_kernel<<<2048, THREADS>>>(w, mask);
    convert_x_kernel<<<8192, THREADS>>>(x);

    dim3 grid(NDIM / BN, MDIM / BM);   // (128, 32)
    gemm_wmma_kernel<<<grid, THREADS>>>(out);
}

// round 4
// speedup vs baseline: 1.5736x; 1.5736x over previous
#include <cuda_runtime.h>
#include <cuda_fp16.h>
#include <cstdint>

// Problem dims
#define BATCH 8
#define SEQ   2048
#define KDIM  4096
#define MDIM  4096
#define NDIM  (BATCH * SEQ)   // 16384

// GEMM tiling: CTA 128x256x64, 8 warps (2m x 4n), warp tile 64x64
#define BM 128
#define BN 256
#define BK 64
#define NST 3
#define GTHREADS 256
#define KITERS (KDIM / BK)    // 64

#define A_BYTES (BM * 128)            // 16384 (128B per row of 64 halfs)
#define B_BYTES (BN * 128)            // 32768
#define STAGE_BYTES (A_BYTES + B_BYTES)   // 49152
#define SMEM_TOTAL (NST * STAGE_BYTES)    // 147456

// fp16 scratch
__device__ __align__(16) __half g_Wh[(size_t)MDIM * KDIM];   // 32 MB
__device__ __align__(16) __half g_Xh[(size_t)NDIM * KDIM];   // 128 MB

// ---------------------------------------------------------------------------
// Conversion kernels (measured 70.8% of HBM spec — leave alone)
// ---------------------------------------------------------------------------
__global__ void convert_w_kernel(const float* __restrict__ w,
                                 const int* __restrict__ mask) {
    size_t total4 = (size_t)MDIM * KDIM / 4;
    for (size_t i = (size_t)blockIdx.x * blockDim.x + threadIdx.x;
         i < total4; i += (size_t)gridDim.x * blockDim.x) {
        float4 wv = reinterpret_cast<const float4*>(w)[i];
        int4   mv = reinterpret_cast<const int4*>(mask)[i];
        float a = mv.x ? wv.x : 0.0f;
        float b = mv.y ? wv.y : 0.0f;
        float c = mv.z ? wv.z : 0.0f;
        float d = mv.w ? wv.w : 0.0f;
        __half2* o = reinterpret_cast<__half2*>(&g_Wh[i * 4]);
        o[0] = __floats2half2_rn(a, b);
        o[1] = __floats2half2_rn(c, d);
    }
}

__global__ void convert_x_kernel(const float* __restrict__ x) {
    size_t total4 = (size_t)NDIM * KDIM / 4;
    for (size_t i = (size_t)blockIdx.x * blockDim.x + threadIdx.x;
         i < total4; i += (size_t)gridDim.x * blockDim.x) {
        float4 xv = reinterpret_cast<const float4*>(x)[i];
        __half2* o = reinterpret_cast<__half2*>(&g_Xh[i * 4]);
        o[0] = __floats2half2_rn(xv.x, xv.y);
        o[1] = __floats2half2_rn(xv.z, xv.w);
    }
}

// ---------------------------------------------------------------------------
// Helpers
// ---------------------------------------------------------------------------
__device__ __forceinline__ uint32_t smem_u32(const void* p) {
    uint32_t a;
    asm("{ .reg .u64 t; cvta.to.shared.u64 t, %1; cvt.u32.u64 %0, t; }"
        : "=r"(a) : "l"(p));
    return a;
}

__device__ __forceinline__ void ldsm_x4(uint32_t& r0, uint32_t& r1,
                                        uint32_t& r2, uint32_t& r3,
                                        uint32_t addr) {
    asm volatile("ldmatrix.sync.aligned.m8n8.x4.shared.b16 {%0,%1,%2,%3}, [%4];"
                 : "=r"(r0), "=r"(r1), "=r"(r2), "=r"(r3) : "r"(addr));
}

__device__ __forceinline__ void mma16816(float* c, uint32_t a0, uint32_t a1,
                                         uint32_t a2, uint32_t a3,
                                         uint32_t b0, uint32_t b1) {
    asm volatile(
        "mma.sync.aligned.m16n8k16.row.col.f32.f16.f16.f32 "
        "{%0,%1,%2,%3}, {%4,%5,%6,%7}, {%8,%9}, {%0,%1,%2,%3};"
        : "+f"(c[0]), "+f"(c[1]), "+f"(c[2]), "+f"(c[3])
        : "r"(a0), "r"(a1), "r"(a2), "r"(a3), "r"(b0), "r"(b1));
}

// ---------------------------------------------------------------------------
// Producer: 3072 x 16B cp.async per stage (A 1024, B 2048), 12 per thread.
// Smem rows are 128B (64 halfs), SW128-swizzled: off ^ ((off>>3)&0x70).
// ---------------------------------------------------------------------------
__device__ __forceinline__ void produce(uint32_t stage, int tid, int j,
                                        int mBase, int nBase) {
    const __half* aseg = &g_Wh[(size_t)mBase * KDIM + j * BK];
    const __half* bseg = &g_Xh[(size_t)nBase * KDIM + j * BK];
#pragma unroll
    for (int t = 0; t < 12; t++) {
        int id = tid + t * GTHREADS;          // 0..3071
        int isB = (id >= 1024);
        int lid = isB ? (id - 1024) : id;
        int row = lid >> 3;
        int c   = lid & 7;
        const __half* src = (isB ? bseg : aseg) + (size_t)row * KDIM + c * 8;
        uint32_t off = row * 128 + c * 16;
        uint32_t dst = stage + (isB ? A_BYTES : 0) + (off ^ ((off >> 3) & 0x70));
        asm volatile("cp.async.cg.shared.global [%0], [%1], 16;"
                     :: "r"(dst), "l"(src) : "memory");
    }
}

// ---------------------------------------------------------------------------
// GEMM: C[m,n] = sum_k Wh[m,k] * Xh[n,k]   (A row-major, B "col-major" = [n][k])
// ---------------------------------------------------------------------------
__global__ void __launch_bounds__(GTHREADS, 1)
gemm_hmma(float* __restrict__ out) {
    extern __shared__ __align__(1024) char smem[];
    const uint32_t sb = smem_u32(smem);
    const int tid = threadIdx.x;
    const int lane = tid & 31;
    const int wid = tid >> 5;
    const int wm = wid >> 2;          // 0..1  (m offset wm*64)
    const int wn = wid & 3;           // 0..3  (n offset wn*64)

    const int mBase = blockIdx.x * BM;
    const int nBase = blockIdx.y * BN;

    // Per-lane ldmatrix offsets (within tile region, before stage base).
    // A x4: lanes 0-7: m rows 0-7 @k0 | 8-15: m 8-15 @k0 | 16-23: m 0-7 @+16B | 24-31: m 8-15 @+16B
    const int aRow = wm * 64 + (lane & 15);
    const uint32_t aOff0 = (uint32_t)aRow * 128 + ((lane >> 4) << 4);
    const uint32_t aMask = ((((uint32_t)aRow * 128) >> 3) & 0x70);
    // B x4: lanes 0-7: n 0-7 @k0 | 8-15: n 0-7 @+16B | 16-23: n 8-15 @k0 | 24-31: n 8-15 @+16B
    const int bRow = wn * 64 + (lane & 7) + ((lane >> 4) << 3);
    const uint32_t bOff0 = (uint32_t)bRow * 128 + (((lane >> 3) & 1) << 4);
    const uint32_t bMask = ((((uint32_t)bRow * 128) >> 3) & 0x70);

    float acc[4][8][4];
#pragma unroll
    for (int i = 0; i < 4; i++)
#pragma unroll
        for (int j = 0; j < 8; j++)
#pragma unroll
            for (int r = 0; r < 4; r++) acc[i][j][r] = 0.0f;

    produce(sb, tid, 0, mBase, nBase);
    asm volatile("cp.async.commit_group;" ::: "memory");
    produce(sb + STAGE_BYTES, tid, 1, mBase, nBase);
    asm volatile("cp.async.commit_group;" ::: "memory");

    for (int i = 0; i < KITERS; i++) {
        asm volatile("cp.async.wait_group 1;" ::: "memory");
        __syncthreads();

        // Prefetch stage i+2 into slot (i+2)%3 (freed by compute of iter i-1)
        if (i + 2 < KITERS)
            produce(sb + ((i + 2) % NST) * STAGE_BYTES, tid, i + 2, mBase, nBase);
        asm volatile("cp.async.commit_group;" ::: "memory");

        const uint32_t stA = sb + (i % NST) * STAGE_BYTES;
        const uint32_t stB = stA + A_BYTES;

#pragma unroll
        for (int kk = 0; kk < 4; kk++) {
            uint32_t a[4][4], b[4][4];
#pragma unroll
            for (int mt = 0; mt < 4; mt++) {           // 4 m16 tiles
                uint32_t off = aOff0 + (uint32_t)mt * 16 * 128 + kk * 32;
                ldsm_x4(a[mt][0], a[mt][1], a[mt][2], a[mt][3],
                        stA + (off ^ aMask));
            }
#pragma unroll
            for (int nt = 0; nt < 4; nt++) {           // 4 n16 groups (= 8 n8)
                uint32_t off = bOff0 + (uint32_t)nt * 16 * 128 + kk * 32;
                ldsm_x4(b[nt][0], b[nt][1], b[nt][2], b[nt][3],
                        stB + (off ^ bMask));
            }
#pragma unroll
            for (int mt = 0; mt < 4; mt++)
#pragma unroll
                for (int nt = 0; nt < 4; nt++) {
                    mma16816(acc[mt][2 * nt],     a[mt][0], a[mt][1], a[mt][2], a[mt][3],
                             b[nt][0], b[nt][1]);
                    mma16816(acc[mt][2 * nt + 1], a[mt][0], a[mt][1], a[mt][2], a[mt][3],
                             b[nt][2], b[nt][3]);
                }
        }
        __syncthreads();
    }

    // Epilogue: direct stores. Each 4-lane group writes one full 32B sector.
    // acc frag: c0,c1 at (row = lane/4, col = 2*(lane%4)+{0,1}); c2,c3 at row+8.
    const int b = nBase / SEQ;
    const int s0 = nBase % SEQ;
    const int mW = mBase + wm * 64;
    const int nW = s0 + wn * 64;
    const int rl = lane >> 2;
    const int cl = (lane & 3) * 2;
#pragma unroll
    for (int mt = 0; mt < 4; mt++) {
#pragma unroll
        for (int j = 0; j < 8; j++) {
            size_t base = ((size_t)b * MDIM + mW + mt * 16 + rl) * SEQ + nW + j * 8 + cl;
            *reinterpret_cast<float2*>(&out[base]) =
                make_float2(acc[mt][j][0], acc[mt][j][1]);
            *reinterpret_cast<float2*>(&out[base + 8 * SEQ]) =
                make_float2(acc[mt][j][2], acc[mt][j][3]);
        }
    }
}

// ---------------------------------------------------------------------------
// Launch
// ---------------------------------------------------------------------------
extern "C" void kernel_launch(void* const* d_in, const int* in_sizes, int n_in,
                              void* d_out, int out_size) {
    const float* x    = (const float*)d_in[0];   // [B, S, K]
    const float* w    = (const float*)d_in[1];   // [M, K]
    const int*   mask = (const int*)d_in[2];     // [M, K] bool -> int32
    float* out = (float*)d_out;                  // [B, M, S]

    convert_w_kernel<<<2048, 256>>>(w, mask);
    convert_x_kernel<<<8192, 256>>>(x);

    cudaFuncSetAttribute(gemm_hmma,
                         cudaFuncAttributeMaxDynamicSharedMemorySize, SMEM_TOTAL);
    dim3 grid(MDIM / BM, NDIM / BN);   // (32, 64): m fastest -> W stays in L2
    gemm_hmma<<<grid, GTHREADS, SMEM_TOTAL>>>(out);
}

// round 5
// speedup vs baseline: 1.5945x; 1.0133x over previous
#include <cuda_runtime.h>
#include <cuda_fp16.h>
#include <cstdint>

// Problem dims
#define BATCH 8
#define SEQ   2048
#define KDIM  4096
#define MDIM  4096
#define NDIM  (BATCH * SEQ)   // 16384

// GEMM tiling: CTA 128x256x64, 8 warps (2m x 4n), warp tile 64x64
#define BM 128
#define BN 256
#define BK 64
#define NST 4
#define GTHREADS 256
#define KITERS (KDIM / BK)    // 64

#define A_BYTES (BM * 128)                 // 16384
#define B_BYTES (BN * 128)                 // 32768
#define STAGE_BYTES (A_BYTES + B_BYTES)    // 49152
#define SMEM_TOTAL (NST * STAGE_BYTES)     // 196608

// fp16 scratch
__device__ __align__(16) __half g_Wh[(size_t)MDIM * KDIM];   // 32 MB
__device__ __align__(16) __half g_Xh[(size_t)NDIM * KDIM];   // 128 MB

// ---------------------------------------------------------------------------
// Conversion kernels (measured ~72% of HBM spec — leave alone)
// ---------------------------------------------------------------------------
__global__ void convert_w_kernel(const float* __restrict__ w,
                                 const int* __restrict__ mask) {
    size_t total4 = (size_t)MDIM * KDIM / 4;
    for (size_t i = (size_t)blockIdx.x * blockDim.x + threadIdx.x;
         i < total4; i += (size_t)gridDim.x * blockDim.x) {
        float4 wv = reinterpret_cast<const float4*>(w)[i];
        int4   mv = reinterpret_cast<const int4*>(mask)[i];
        float a = mv.x ? wv.x : 0.0f;
        float b = mv.y ? wv.y : 0.0f;
        float c = mv.z ? wv.z : 0.0f;
        float d = mv.w ? wv.w : 0.0f;
        __half2* o = reinterpret_cast<__half2*>(&g_Wh[i * 4]);
        o[0] = __floats2half2_rn(a, b);
        o[1] = __floats2half2_rn(c, d);
    }
}

__global__ void convert_x_kernel(const float* __restrict__ x) {
    size_t total4 = (size_t)NDIM * KDIM / 4;
    for (size_t i = (size_t)blockIdx.x * blockDim.x + threadIdx.x;
         i < total4; i += (size_t)gridDim.x * blockDim.x) {
        float4 xv = reinterpret_cast<const float4*>(x)[i];
        __half2* o = reinterpret_cast<__half2*>(&g_Xh[i * 4]);
        o[0] = __floats2half2_rn(xv.x, xv.y);
        o[1] = __floats2half2_rn(xv.z, xv.w);
    }
}

// ---------------------------------------------------------------------------
// Helpers
// ---------------------------------------------------------------------------
__device__ __forceinline__ uint32_t smem_u32(const void* p) {
    uint32_t a;
    asm("{ .reg .u64 t; cvta.to.shared.u64 t, %1; cvt.u32.u64 %0, t; }"
        : "=r"(a) : "l"(p));
    return a;
}

__device__ __forceinline__ void ldsm_x4(uint32_t& r0, uint32_t& r1,
                                        uint32_t& r2, uint32_t& r3,
                                        uint32_t addr) {
    asm volatile("ldmatrix.sync.aligned.m8n8.x4.shared.b16 {%0,%1,%2,%3}, [%4];"
                 : "=r"(r0), "=r"(r1), "=r"(r2), "=r"(r3) : "r"(addr));
}

__device__ __forceinline__ void mma16816(float* c, const uint32_t* a,
                                         uint32_t b0, uint32_t b1) {
    asm volatile(
        "mma.sync.aligned.m16n8k16.row.col.f32.f16.f16.f32 "
        "{%0,%1,%2,%3}, {%4,%5,%6,%7}, {%8,%9}, {%0,%1,%2,%3};"
        : "+f"(c[0]), "+f"(c[1]), "+f"(c[2]), "+f"(c[3])
        : "r"(a[0]), "r"(a[1]), "r"(a[2]), "r"(a[3]), "r"(b0), "r"(b1));
}

// ---------------------------------------------------------------------------
// Producer: 3072 x 16B cp.async per stage (A 1024, B 2048), 12 per thread.
// ---------------------------------------------------------------------------
__device__ __forceinline__ void produce(uint32_t stage, int tid, int j,
                                        int mBase, int nBase) {
    const __half* aseg = &g_Wh[(size_t)mBase * KDIM + j * BK];
    const __half* bseg = &g_Xh[(size_t)nBase * KDIM + j * BK];
#pragma unroll
    for (int t = 0; t < 12; t++) {
        int id = tid + t * GTHREADS;          // 0..3071
        int isB = (id >= 1024);
        int lid = isB ? (id - 1024) : id;
        int row = lid >> 3;
        int c   = lid & 7;
        const __half* src = (isB ? bseg : aseg) + (size_t)row * KDIM + c * 8;
        uint32_t off = row * 128 + c * 16;
        uint32_t dst = stage + (isB ? A_BYTES : 0) + (off ^ ((off >> 3) & 0x70));
        asm volatile("cp.async.cg.shared.global [%0], [%1], 16;"
                     :: "r"(dst), "l"(src) : "memory");
    }
}

// ---------------------------------------------------------------------------
// GEMM: C[m,n] = sum_k Wh[m,k] * Xh[n,k]
// ---------------------------------------------------------------------------
__global__ void __launch_bounds__(GTHREADS, 1)
gemm_hmma(float* __restrict__ out) {
    extern __shared__ __align__(1024) char smem[];
    const uint32_t sb = smem_u32(smem);
    const int tid = threadIdx.x;
    const int lane = tid & 31;
    const int wid = tid >> 5;
    const int wm = wid >> 2;          // 0..1
    const int wn = wid & 3;           // 0..3

    const int mBase = blockIdx.x * BM;
    const int nBase = blockIdx.y * BN;

    // Per-lane ldmatrix base offsets (swizzle mask precomputed per lane row)
    const int aRow = wm * 64 + (lane & 15);
    const uint32_t aOff0 = (uint32_t)aRow * 128 + ((lane >> 4) << 4);
    const uint32_t aMask = ((((uint32_t)aRow * 128) >> 3) & 0x70);
    const int bRow = wn * 64 + (lane & 7) + ((lane >> 4) << 3);
    const uint32_t bOff0 = (uint32_t)bRow * 128 + (((lane >> 3) & 1) << 4);
    const uint32_t bMask = ((((uint32_t)bRow * 128) >> 3) & 0x70);

    float acc[4][8][4];
#pragma unroll
    for (int i = 0; i < 4; i++)
#pragma unroll
        for (int j = 0; j < 8; j++)
#pragma unroll
            for (int r = 0; r < 4; r++) acc[i][j][r] = 0.0f;

    // Prefill 3 of 4 stages
    produce(sb + 0 * STAGE_BYTES, tid, 0, mBase, nBase);
    asm volatile("cp.async.commit_group;" ::: "memory");
    produce(sb + 1 * STAGE_BYTES, tid, 1, mBase, nBase);
    asm volatile("cp.async.commit_group;" ::: "memory");
    produce(sb + 2 * STAGE_BYTES, tid, 2, mBase, nBase);
    asm volatile("cp.async.commit_group;" ::: "memory");

    for (int i = 0; i < KITERS; i++) {
        asm volatile("cp.async.wait_group 2;" ::: "memory");
        __syncthreads();   // sole barrier per iter: orders fills AND frees old slot

        if (i + 3 < KITERS)
            produce(sb + ((i + 3) % NST) * STAGE_BYTES, tid, i + 3, mBase, nBase);
        asm volatile("cp.async.commit_group;" ::: "memory");

        const uint32_t stA = sb + (i % NST) * STAGE_BYTES;
        const uint32_t stB = stA + A_BYTES;

        // Double-buffered fragments across kk: load kk+1 while issuing kk's MMAs
        uint32_t a[2][4][4], b[2][4][4];
#pragma unroll
        for (int mt = 0; mt < 4; mt++) {
            uint32_t off = aOff0 + (uint32_t)mt * 16 * 128;
            ldsm_x4(a[0][mt][0], a[0][mt][1], a[0][mt][2], a[0][mt][3],
                    stA + (off ^ aMask));
        }
#pragma unroll
        for (int nt = 0; nt < 4; nt++) {
            uint32_t off = bOff0 + (uint32_t)nt * 16 * 128;
            ldsm_x4(b[0][nt][0], b[0][nt][1], b[0][nt][2], b[0][nt][3],
                    stB + (off ^ bMask));
        }

#pragma unroll
        for (int kk = 0; kk < 4; kk++) {
            const int cur = kk & 1, nxt = cur ^ 1;
            if (kk < 3) {
#pragma unroll
                for (int mt = 0; mt < 4; mt++) {
                    uint32_t off = aOff0 + (uint32_t)mt * 16 * 128 + (kk + 1) * 32;
                    ldsm_x4(a[nxt][mt][0], a[nxt][mt][1], a[nxt][mt][2], a[nxt][mt][3],
                            stA + (off ^ aMask));
                }
#pragma unroll
                for (int nt = 0; nt < 4; nt++) {
                    uint32_t off = bOff0 + (uint32_t)nt * 16 * 128 + (kk + 1) * 32;
                    ldsm_x4(b[nxt][nt][0], b[nxt][nt][1], b[nxt][nt][2], b[nxt][nt][3],
                            stB + (off ^ bMask));
                }
            }
#pragma unroll
            for (int mt = 0; mt < 4; mt++)
#pragma unroll
                for (int nt = 0; nt < 4; nt++) {
                    mma16816(acc[mt][2 * nt],     a[cur][mt], b[cur][nt][0], b[cur][nt][1]);
                    mma16816(acc[mt][2 * nt + 1], a[cur][mt], b[cur][nt][2], b[cur][nt][3]);
                }
        }
        // no bottom barrier: next iter's top barrier orders slot reuse
    }

    // Epilogue: direct stores; each 4-lane group writes a full 32B sector.
    const int b2 = nBase / SEQ;
    const int s0 = nBase % SEQ;
    const int mW = mBase + wm * 64;
    const int nW = s0 + wn * 64;
    const int rl = lane >> 2;
    const int cl = (lane & 3) * 2;
#pragma unroll
    for (int mt = 0; mt < 4; mt++) {
#pragma unroll
        for (int j = 0; j < 8; j++) {
            size_t base = ((size_t)b2 * MDIM + mW + mt * 16 + rl) * SEQ + nW + j * 8 + cl;
            *reinterpret_cast<float2*>(&out[base]) =
                make_float2(acc[mt][j][0], acc[mt][j][1]);
            *reinterpret_cast<float2*>(&out[base + 8 * SEQ]) =
                make_float2(acc[mt][j][2], acc[mt][j][3]);
        }
    }
}

// ---------------------------------------------------------------------------
// Launch
// ---------------------------------------------------------------------------
extern "C" void kernel_launch(void* const* d_in, const int* in_sizes, int n_in,
                              void* d_out, int out_size) {
    const float* x    = (const float*)d_in[0];   // [B, S, K]
    const float* w    = (const float*)d_in[1];   // [M, K]
    const int*   mask = (const int*)d_in[2];     // [M, K] bool -> int32
    float* out = (float*)d_out;                  // [B, M, S]

    convert_w_kernel<<<2048, 256>>>(w, mask);
    convert_x_kernel<<<8192, 256>>>(x);

    cudaFuncSetAttribute(gemm_hmma,
                         cudaFuncAttributeMaxDynamicSharedMemorySize, SMEM_TOTAL);
    dim3 grid(MDIM / BM, NDIM / BN);   // (32, 64): m fastest -> W stays in L2
    gemm_hmma<<<grid, GTHREADS, SMEM_TOTAL>>>(out);
}